// round 6
// baseline (speedup 1.0000x reference)
#include <cuda_runtime.h>
#include <cuda_bf16.h>
#include <math.h>

// ---------------------------------------------------------------------------
// Decoder layer, B=1, S=2048, D=4096, H=32, HKV=8, HD=128, FF=11008
// Round 4: 3xBF16 split tensor-core GEMMs (half the tensor cycles of 3xTF32),
// fused QKV launch, tf32 softmax-PV, fused SwiGLU epilogue.
// ---------------------------------------------------------------------------

#define S_LEN 2048
#define D_DIM 4096
#define H_HEADS 32
#define HKV_HEADS 8
#define HD_DIM 128
#define FF_DIM 11008
#define GAMMA_C 64.0f
#define EPS_C 1e-5f

#define SD   (2048LL*4096LL)
#define SKV  (2048LL*1024LL)
#define SH   (32LL*2048LL*128LL)
#define SFF  (2048LL*11008LL)

#define O_X    0LL
#define O_Q    (O_X  + SD)
#define O_K    (O_Q  + SD)
#define O_V    (O_K  + SKV)
#define O_QR   (O_V  + SKV)
#define O_KR   (O_QR + SD)
#define O_QH   (O_KR + SKV)
#define O_KH   (O_QH + SH)
#define O_AO   (O_KH + SH)
#define O_H1   (O_AO + SD)
#define O_Y    (O_H1 + SD)
#define O_G    (O_Y  + SD)
#define O_U    (O_G  + SFF)
#define O_COS  (O_U  + SFF)
#define O_SIN  (O_COS + 2048LL*64LL)
#define O_MX   (O_SIN + 2048LL*64LL)
#define SCRATCH_TOTAL (O_MX + 32LL*2048LL)

__device__ float g_scratch[SCRATCH_TOTAL];

// ---------------------------------------------------------------------------
// helpers
// ---------------------------------------------------------------------------
__device__ __forceinline__ unsigned f2tf(float x) {
    unsigned r;
    asm("cvt.rna.tf32.f32 %0, %1;" : "=r"(r) : "f"(x));
    return r;
}

// pack (f.x -> low bf16, f.y -> high bf16), plus residual pack
__device__ __forceinline__ void pack_split(float2 f, unsigned& hi, unsigned& lo) {
    unsigned h;
    asm("cvt.rn.bf16x2.f32 %0, %1, %2;" : "=r"(h) : "f"(f.y), "f"(f.x));
    float hx = __uint_as_float(h << 16);
    float hy = __uint_as_float(h & 0xffff0000u);
    float lx = f.x - hx;
    float ly = f.y - hy;
    unsigned l;
    asm("cvt.rn.bf16x2.f32 %0, %1, %2;" : "=r"(l) : "f"(ly), "f"(lx));
    hi = h; lo = l;
}

__device__ __forceinline__ void mma16bf(float* c, const unsigned* a, const unsigned* b) {
    asm volatile(
        "mma.sync.aligned.m16n8k16.row.col.f32.bf16.bf16.f32 "
        "{%0,%1,%2,%3},{%4,%5,%6,%7},{%8,%9},{%0,%1,%2,%3};"
        : "+f"(c[0]), "+f"(c[1]), "+f"(c[2]), "+f"(c[3])
        : "r"(a[0]), "r"(a[1]), "r"(a[2]), "r"(a[3]), "r"(b[0]), "r"(b[1]));
}

__device__ __forceinline__ void mma8tf(float* c, const unsigned* a,
                                       unsigned b0, unsigned b1) {
    asm volatile(
        "mma.sync.aligned.m16n8k8.row.col.f32.tf32.tf32.f32 "
        "{%0,%1,%2,%3},{%4,%5,%6,%7},{%8,%9},{%0,%1,%2,%3};"
        : "+f"(c[0]), "+f"(c[1]), "+f"(c[2]), "+f"(c[3])
        : "r"(a[0]), "r"(a[1]), "r"(a[2]), "r"(a[3]), "r"(b0), "r"(b1));
}

#define CP16(d, s) asm volatile("cp.async.cg.shared.global [%0], [%1], 16;" :: "r"(d), "l"(s))
#define CP_COMMIT() asm volatile("cp.async.commit_group;")
#define CP_WAIT0()  asm volatile("cp.async.wait_group 0;")

// ---------------------------------------------------------------------------
// RoPE tables in fp64
// ---------------------------------------------------------------------------
__global__ void rope_table_kernel(float* cosT, float* sinT) {
    int s = blockIdx.x;
    int i = threadIdx.x; // 0..63
    double inv = exp(-(double)i * (log(10000.0) / 64.0));
    double ang = (double)s * inv;
    double sv, cv;
    sincos(ang, &sv, &cv);
    cosT[s * 64 + i] = (float)cv;
    sinT[s * 64 + i] = (float)sv;
}

// ---------------------------------------------------------------------------
// RMSNorm
// ---------------------------------------------------------------------------
__global__ void rmsnorm_kernel(const float* __restrict__ x,
                               const float* __restrict__ w,
                               float* __restrict__ out) {
    int s = blockIdx.x;
    const float* row = x + (long long)s * D_DIM;
    float* orow = out + (long long)s * D_DIM;
    int tid = threadIdx.x;
    float ss = 0.f;
    for (int i = tid; i < D_DIM; i += 256) {
        float v = row[i];
        ss += v * v;
    }
    __shared__ float red[256];
    red[tid] = ss;
    __syncthreads();
    for (int o = 128; o > 0; o >>= 1) {
        if (tid < o) red[tid] += red[tid + o];
        __syncthreads();
    }
    float inv = rsqrtf(red[0] / (float)D_DIM + EPS_C);
    for (int i = tid; i < D_DIM; i += 256)
        orow[i] = row[i] * inv * w[i];
}

// ---------------------------------------------------------------------------
// RoPE apply
// ---------------------------------------------------------------------------
__global__ void rope_apply_kernel(const float* __restrict__ in,
                                  float* __restrict__ out,
                                  const float* __restrict__ cosT,
                                  const float* __restrict__ sinT,
                                  int nHeads) {
    int s = blockIdx.x;
    int h = blockIdx.y;
    int d = threadIdx.x; // 0..127
    int ld = nHeads * HD_DIM;
    long long base = (long long)s * ld + h * HD_DIM;
    float x = in[base + d];
    float other = (d < 64) ? -in[base + d + 64] : in[base + d - 64];
    float c = cosT[s * 64 + (d & 63)];
    float sn = sinT[s * 64 + (d & 63)];
    out[base + d] = x * c + other * sn;
}

// ---------------------------------------------------------------------------
// row max over causal prefix of true_attn rows
// ---------------------------------------------------------------------------
__global__ void rowmax_kernel(const float* __restrict__ t, float* __restrict__ mx) {
    int r = blockIdx.x * 8 + threadIdx.y;  // 0 .. H*S-1
    int s = r & (S_LEN - 1);
    const float* row = t + (long long)r * S_LEN;
    float m = -1e30f;
    for (int i = threadIdx.x; i <= s; i += 32) m = fmaxf(m, row[i]);
#pragma unroll
    for (int o = 16; o > 0; o >>= 1) m = fmaxf(m, __shfl_xor_sync(0xffffffffu, m, o));
    if (threadIdx.x == 0) mx[r] = m;
}

// ---------------------------------------------------------------------------
// Tensor-core GEMM, 128x128x32 tile, 8 warps (2x4), warp tile 64x32.
// MODE 0: single tf32 (m16n8k8)        -- used for softmax-PV
// MODE 1: 3-term bf16 split (m16n8k16) -- fp32-ish accuracy, half tensor cost
// TRANSB=false: C[m,n] = sum_k A[m,k]*B[k,n];  true: B[n,k].
// EPI: 0 store, 1 alpha*acc, 2 hash-sat, 3 acc+R, 4 softmax-PV, 5 silu(R)*acc
// Optional fused-QKV: Bq2/Bq3/Cq2/Cq3 non-null -> blocks with col0>=4096 remap.
// ---------------------------------------------------------------------------
#define BM 128
#define BN 128
#define BKT 32
#define ASTR 36
#define BSTR_NN 136
#define ABUF (BM * ASTR)
#define BBUF (BM * ASTR)
#define SMEM_FLOATS (2 * ABUF + 2 * BBUF + 128 + 128 + 256)
#define SMEM_BYTES (SMEM_FLOATS * 4)

template <int MODE, bool TRANSB, int EPI>
__global__ __launch_bounds__(256)
void gemm_tc(const float* __restrict__ A, const float* __restrict__ Bin,
             float* __restrict__ Cin, const float* __restrict__ R,
             const float* __restrict__ stats,
             int M, int N, int K, int lda, int ldbIn, int ldcIn,
             long long strideA, int aRep,
             long long strideB, int bRep,
             long long strideC, float alpha,
             const float* __restrict__ Bq2, const float* __restrict__ Bq3,
             float* __restrict__ Cq2, float* __restrict__ Cq3) {
    extern __shared__ float smem[];
    float* As = smem;
    float* Bs = smem + 2 * ABUF;
    float* sMax = smem + 2 * ABUF + 2 * BBUF;
    float* sSum = sMax + 128;
    float* sPart = sSum + 128;

    int z = blockIdx.z;
    A += (long long)(z / aRep) * strideA;
    const float* B = Bin + (long long)(z / bRep) * strideB;
    float* C = Cin + (long long)z * strideC;
    int ldb = ldbIn, ldc = ldcIn;
    int col0 = blockIdx.x * BN;

    if (Bq2 != nullptr) { // fused QKV remap
        if (col0 >= 5120) { B = Bq3; C = Cq3; ldb = 1024; ldc = 1024; col0 -= 5120; }
        else if (col0 >= 4096) { B = Bq2; C = Cq2; ldb = 1024; ldc = 1024; col0 -= 4096; }
    }

    const int tid = threadIdx.x;
    const int row0 = blockIdx.y * BM;
    const int warp = tid >> 5;
    const int lane = tid & 31;
    const int gid = lane >> 2;
    const int t4 = lane & 3;
    const int wm = (warp & 1) * 64;
    const int wn = (warp >> 1) * 32;

    if (EPI == 4) {
        if (tid < 128) {
            sMax[tid] = stats[(long long)z * M + row0 + tid];
            sSum[tid] = 0.f;
        }
        __syncthreads();
    }

    float acc[4][4][4];
#pragma unroll
    for (int i = 0; i < 4; i++)
#pragma unroll
        for (int j = 0; j < 4; j++)
#pragma unroll
            for (int q = 0; q < 4; q++) acc[i][j][q] = 0.f;

    int Kend = (EPI == 4) ? ((row0 + BM < K) ? row0 + BM : K) : K;
    int nIter = Kend / BKT;

    const int arow = tid >> 1, acol = (tid & 1) * 16;
    const int brow = tid >> 3, bcol = (tid & 7) * 16;

    // prologue: stage 0
    {
        const float* src = A + (long long)(row0 + arow) * lda + acol;
        unsigned dst = (unsigned)__cvta_generic_to_shared(As + arow * ASTR + acol);
#pragma unroll
        for (int i = 0; i < 4; i++) CP16(dst + i * 16, src + i * 4);
        if (TRANSB) {
            const float* bs = B + (long long)(col0 + arow) * ldb + acol;
            unsigned bd = (unsigned)__cvta_generic_to_shared(Bs + arow * ASTR + acol);
#pragma unroll
            for (int i = 0; i < 4; i++) CP16(bd + i * 16, bs + i * 4);
        } else {
            const float* bs = B + (long long)brow * ldb + col0 + bcol;
            unsigned bd = (unsigned)__cvta_generic_to_shared(Bs + brow * BSTR_NN + bcol);
#pragma unroll
            for (int i = 0; i < 4; i++) CP16(bd + i * 16, bs + i * 4);
        }
        CP_COMMIT();
    }

    for (int it = 0; it < nIter; it++) {
        int buf = it & 1;
        CP_WAIT0();
        __syncthreads();

        if (EPI == 4) {
            // softmax transform of A tile in smem, one exp per element
            int r = tid >> 1, c0 = (tid & 1) * 16;
            float* p = As + buf * ABUF + r * ASTR + c0;
            int gm = row0 + r;
            float mxv = sMax[r];
            int k0 = it * BKT;
            float part = 0.f;
#pragma unroll
            for (int i = 0; i < 16; i++) {
                int gk = k0 + c0 + i;
                float val = 0.f;
                if (gk <= gm) val = __expf(p[i] - mxv);
                val = __uint_as_float(f2tf(val));
                p[i] = val;
                part += val;
            }
            sPart[tid] = part;
            __syncthreads();
            if (tid < 128) sSum[tid] += sPart[2 * tid] + sPart[2 * tid + 1];
            __syncthreads();
        }

        if (it + 1 < nIter) {
            int k0n = (it + 1) * BKT;
            int nb = buf ^ 1;
            const float* src = A + (long long)(row0 + arow) * lda + k0n + acol;
            unsigned dst = (unsigned)__cvta_generic_to_shared(As + nb * ABUF + arow * ASTR + acol);
#pragma unroll
            for (int i = 0; i < 4; i++) CP16(dst + i * 16, src + i * 4);
            if (TRANSB) {
                const float* bs = B + (long long)(col0 + arow) * ldb + k0n + acol;
                unsigned bd = (unsigned)__cvta_generic_to_shared(Bs + nb * BBUF + arow * ASTR + acol);
#pragma unroll
                for (int i = 0; i < 4; i++) CP16(bd + i * 16, bs + i * 4);
            } else {
                const float* bs = B + (long long)(k0n + brow) * ldb + col0 + bcol;
                unsigned bd = (unsigned)__cvta_generic_to_shared(Bs + nb * BBUF + brow * BSTR_NN + bcol);
#pragma unroll
                for (int i = 0; i < 4; i++) CP16(bd + i * 16, bs + i * 4);
            }
            CP_COMMIT();
        }

        const float* Ab = As + buf * ABUF;
        const float* Bb = Bs + buf * BBUF;

        if (MODE == 1) {
            // ---- 3xBF16 split path, two k16 steps ----
#pragma unroll
            for (int ks = 0; ks < 2; ks++) {
                int k = ks * 16;
                unsigned ah[4][4], al[4][4];
#pragma unroll
                for (int i = 0; i < 4; i++) {
                    const float* ap = Ab + (wm + i * 16 + gid) * ASTR + k + 2 * t4;
                    float2 p0 = *(const float2*)(ap);
                    float2 p1 = *(const float2*)(ap + 8 * ASTR);
                    float2 p2 = *(const float2*)(ap + 8);
                    float2 p3 = *(const float2*)(ap + 8 * ASTR + 8);
                    pack_split(p0, ah[i][0], al[i][0]);
                    pack_split(p1, ah[i][1], al[i][1]);
                    pack_split(p2, ah[i][2], al[i][2]);
                    pack_split(p3, ah[i][3], al[i][3]);
                }
                unsigned bh[4][2], bl[4][2];
#pragma unroll
                for (int j = 0; j < 4; j++) {
                    float2 q0, q1;
                    if (TRANSB) {
                        const float* bp = Bb + (wn + j * 8 + gid) * ASTR + k + 2 * t4;
                        q0 = *(const float2*)(bp);
                        q1 = *(const float2*)(bp + 8);
                    } else {
                        const float* bp = Bb + (k + 2 * t4) * BSTR_NN + wn + j * 8 + gid;
                        q0.x = bp[0];
                        q0.y = bp[BSTR_NN];
                        q1.x = bp[8 * BSTR_NN];
                        q1.y = bp[9 * BSTR_NN];
                    }
                    pack_split(q0, bh[j][0], bl[j][0]);
                    pack_split(q1, bh[j][1], bl[j][1]);
                }
#pragma unroll
                for (int i = 0; i < 4; i++)
#pragma unroll
                    for (int j = 0; j < 4; j++) {
                        mma16bf(acc[i][j], ah[i], bh[j]);
                        mma16bf(acc[i][j], ah[i], bl[j]);
                        mma16bf(acc[i][j], al[i], bh[j]);
                    }
            }
        } else {
            // ---- single tf32 path (PV), four k8 steps ----
#pragma unroll
            for (int ks = 0; ks < 4; ks++) {
                int k = ks * 8;
                unsigned af[4][4];
#pragma unroll
                for (int i = 0; i < 4; i++) {
                    const float* ap = Ab + (wm + i * 16 + gid) * ASTR + k + t4;
                    af[i][0] = f2tf(ap[0]);
                    af[i][1] = f2tf(ap[8 * ASTR]);
                    af[i][2] = f2tf(ap[4]);
                    af[i][3] = f2tf(ap[8 * ASTR + 4]);
                }
                unsigned bf2[4][2];
#pragma unroll
                for (int j = 0; j < 4; j++) {
                    if (TRANSB) {
                        const float* bp = Bb + (wn + j * 8 + gid) * ASTR + k + t4;
                        bf2[j][0] = f2tf(bp[0]);
                        bf2[j][1] = f2tf(bp[4]);
                    } else {
                        const float* bp = Bb + (k + t4) * BSTR_NN + wn + j * 8 + gid;
                        bf2[j][0] = f2tf(bp[0]);
                        bf2[j][1] = f2tf(bp[4 * BSTR_NN]);
                    }
                }
#pragma unroll
                for (int i = 0; i < 4; i++)
#pragma unroll
                    for (int j = 0; j < 4; j++)
                        mma8tf(acc[i][j], af[i], bf2[j][0], bf2[j][1]);
            }
        }
    }

    // epilogue
#pragma unroll
    for (int i = 0; i < 4; i++)
#pragma unroll
        for (int j = 0; j < 4; j++)
#pragma unroll
            for (int h = 0; h < 2; h++) {
                int lr = wm + i * 16 + gid + h * 8;
                int r = row0 + lr;
                int c = col0 + wn + j * 8 + t4 * 2;
                float v0 = acc[i][j][h * 2 + 0];
                float v1 = acc[i][j][h * 2 + 1];
                long long off = (long long)r * ldc + c;
                if (EPI == 1) {
                    v0 *= alpha; v1 *= alpha;
                } else if (EPI == 2) {
                    v0 *= alpha; v1 *= alpha;
                    v0 = v0 / (1.f + fabsf(v0));
                    v1 = v1 / (1.f + fabsf(v1));
                } else if (EPI == 3) {
                    float2 rr = *(const float2*)(R + off);
                    v0 += rr.x; v1 += rr.y;
                } else if (EPI == 4) {
                    float sdiv = sSum[lr];
                    v0 /= sdiv; v1 /= sdiv;
                } else if (EPI == 5) {
                    float2 rr = *(const float2*)(R + off);
                    float s0 = rr.x / (1.f + __expf(-rr.x));
                    float s1 = rr.y / (1.f + __expf(-rr.y));
                    v0 *= s0; v1 *= s1;
                }
                float2 o2;
                o2.x = v0; o2.y = v1;
                *(float2*)(C + off) = o2;
            }
}

// ---------------------------------------------------------------------------
// launch
// ---------------------------------------------------------------------------
extern "C" void kernel_launch(void* const* d_in, const int* in_sizes, int n_in,
                              void* d_out, int out_size) {
    const float* hidden_states = (const float*)d_in[0];
    const float* ln1_w = (const float*)d_in[1];
    const float* ln2_w = (const float*)d_in[2];
    const float* Wq = (const float*)d_in[3];
    const float* Wk = (const float*)d_in[4];
    const float* Wv = (const float*)d_in[5];
    const float* Wo = (const float*)d_in[6];
    const float* rot_mat = (const float*)d_in[7];
    const float* Wg = (const float*)d_in[8];
    const float* Wu = (const float*)d_in[9];
    const float* Wd = (const float*)d_in[10];

    float* out = (float*)d_out;
    float* out_hidden = out;
    float* out_draft = out + SD;
    float* out_true = out + SD + (long long)H_HEADS * S_LEN * S_LEN;

    float* sc = nullptr;
    cudaGetSymbolAddress((void**)&sc, g_scratch);
    float* g_x  = sc + O_X;
    float* g_q  = sc + O_Q;
    float* g_k  = sc + O_K;
    float* g_v  = sc + O_V;
    float* g_qr = sc + O_QR;
    float* g_kr = sc + O_KR;
    float* g_qh = sc + O_QH;
    float* g_kh = sc + O_KH;
    float* g_ao = sc + O_AO;
    float* g_h1 = sc + O_H1;
    float* g_y  = sc + O_Y;
    float* g_g  = sc + O_G;
    float* g_u  = sc + O_U;
    float* g_cos = sc + O_COS;
    float* g_sin = sc + O_SIN;
    float* g_mx = sc + O_MX;

    const float scale = 0.08838834764831843f; // 1/sqrt(128)

    cudaFuncSetAttribute(gemm_tc<1, false, 0>, cudaFuncAttributeMaxDynamicSharedMemorySize, SMEM_BYTES);
    cudaFuncSetAttribute(gemm_tc<1, false, 2>, cudaFuncAttributeMaxDynamicSharedMemorySize, SMEM_BYTES);
    cudaFuncSetAttribute(gemm_tc<1, false, 3>, cudaFuncAttributeMaxDynamicSharedMemorySize, SMEM_BYTES);
    cudaFuncSetAttribute(gemm_tc<0, false, 4>, cudaFuncAttributeMaxDynamicSharedMemorySize, SMEM_BYTES);
    cudaFuncSetAttribute(gemm_tc<1, false, 5>, cudaFuncAttributeMaxDynamicSharedMemorySize, SMEM_BYTES);
    cudaFuncSetAttribute(gemm_tc<1, true, 0>, cudaFuncAttributeMaxDynamicSharedMemorySize, SMEM_BYTES);
    cudaFuncSetAttribute(gemm_tc<1, true, 1>, cudaFuncAttributeMaxDynamicSharedMemorySize, SMEM_BYTES);

    rope_table_kernel<<<S_LEN, 64>>>(g_cos, g_sin);
    rmsnorm_kernel<<<S_LEN, 256>>>(hidden_states, ln1_w, g_x);

    // Fused QKV projection: N = 4096 | 1024 | 1024 -> grid.x = 48
    gemm_tc<1, false, 0><<<dim3(48, 16, 1), 256, SMEM_BYTES>>>(
        g_x, Wq, g_q, nullptr, nullptr, S_LEN, 6144, 4096, 4096, 4096, 4096,
        0, 1, 0, 1, 0, 0.f, Wk, Wv, g_k, g_v);

    // RoPE
    rope_apply_kernel<<<dim3(S_LEN, H_HEADS), 128>>>(g_q, g_qr, g_cos, g_sin, H_HEADS);
    rope_apply_kernel<<<dim3(S_LEN, HKV_HEADS), 128>>>(g_k, g_kr, g_cos, g_sin, HKV_HEADS);

    // LSH hash (bf16 split)
    gemm_tc<1, false, 2><<<dim3(1, 16, 32), 256, SMEM_BYTES>>>(
        g_qr, rot_mat, g_qh, nullptr, nullptr, S_LEN, 128, 128, 4096, 128, 128,
        128, 1, 128LL * 128, 1, 2048LL * 128, GAMMA_C, nullptr, nullptr, nullptr, nullptr);
    gemm_tc<1, false, 2><<<dim3(1, 16, 32), 256, SMEM_BYTES>>>(
        g_kr, rot_mat, g_kh, nullptr, nullptr, S_LEN, 128, 128, 1024, 128, 128,
        128, 4, 128LL * 128, 1, 2048LL * 128, GAMMA_C, nullptr, nullptr, nullptr, nullptr);

    // draft_attn = q_hash @ k_hash^T (bf16 split)
    gemm_tc<1, true, 0><<<dim3(16, 16, 32), 256, SMEM_BYTES>>>(
        g_qh, g_kh, out_draft, nullptr, nullptr, S_LEN, S_LEN, 128, 128, 128, S_LEN,
        2048LL * 128, 1, 2048LL * 128, 1, (long long)S_LEN * S_LEN, 0.f,
        nullptr, nullptr, nullptr, nullptr);

    // true_attn = scale * q_r @ k_r^T (bf16 split)
    gemm_tc<1, true, 1><<<dim3(16, 16, 32), 256, SMEM_BYTES>>>(
        g_qr, g_kr, out_true, nullptr, nullptr, S_LEN, S_LEN, 128, 4096, 1024, S_LEN,
        128, 1, 128, 4, (long long)S_LEN * S_LEN, scale,
        nullptr, nullptr, nullptr, nullptr);

    // causal row max
    rowmax_kernel<<<H_HEADS * S_LEN / 8, dim3(32, 8)>>>(out_true, g_mx);

    // PV: softmax in A-transform (single tf32)
    gemm_tc<0, false, 4><<<dim3(1, 16, 32), 256, SMEM_BYTES>>>(
        out_true, g_v, g_ao, nullptr, g_mx, S_LEN, 128, S_LEN, S_LEN, 1024, 4096,
        (long long)S_LEN * S_LEN, 1, 128, 4, 128, 0.f,
        nullptr, nullptr, nullptr, nullptr);

    // o_proj + residual (bf16 split)
    gemm_tc<1, false, 3><<<dim3(32, 16, 1), 256, SMEM_BYTES>>>(
        g_ao, Wo, g_h1, hidden_states, nullptr, S_LEN, 4096, 4096, 4096, 4096, 4096,
        0, 1, 0, 1, 0, 0.f, nullptr, nullptr, nullptr, nullptr);

    rmsnorm_kernel<<<S_LEN, 256>>>(g_h1, ln2_w, g_y);

    // MLP: gate, up (fused silu(g)*u), down + residual (bf16 split)
    gemm_tc<1, false, 0><<<dim3(86, 16, 1), 256, SMEM_BYTES>>>(
        g_y, Wg, g_g, nullptr, nullptr, S_LEN, FF_DIM, 4096, 4096, FF_DIM, FF_DIM,
        0, 1, 0, 1, 0, 0.f, nullptr, nullptr, nullptr, nullptr);
    gemm_tc<1, false, 5><<<dim3(86, 16, 1), 256, SMEM_BYTES>>>(
        g_y, Wu, g_u, g_g, nullptr, S_LEN, FF_DIM, 4096, 4096, FF_DIM, FF_DIM,
        0, 1, 0, 1, 0, 0.f, nullptr, nullptr, nullptr, nullptr);
    gemm_tc<1, false, 3><<<dim3(32, 16, 1), 256, SMEM_BYTES>>>(
        g_u, Wd, out_hidden, g_h1, nullptr, S_LEN, 4096, FF_DIM, FF_DIM, 4096, 4096,
        0, 1, 0, 1, 0, 0.f, nullptr, nullptr, nullptr, nullptr);

    (void)in_sizes; (void)n_in; (void)out_size;
}

// round 10
// speedup vs baseline: 1.9642x; 1.9642x over previous
#include <cuda_runtime.h>
#include <cuda_bf16.h>
#include <math.h>

// ---------------------------------------------------------------------------
// Decoder layer, B=1, S=2048, D=4096, H=32, HKV=8, HD=128, FF=11008
// Round 6 resubmit (container infra flake): R5 design with the A-fragment
// smem offset bug fixed (8-row offset was 8*(BSTR/2)*16 == whole-stage
// stride -> read race garbage). All GEMMs TN bf16 3-term split, operands
// pre-split hi/lo in gmem. PV stays tf32 with in-smem softmax.
// ---------------------------------------------------------------------------

#define S_LEN 2048
#define D_DIM 4096
#define H_HEADS 32
#define HKV_HEADS 8
#define HD_DIM 128
#define FF_DIM 11008
#define GAMMA_C 64.0f
#define EPS_C 1e-5f

// ---------------- f32 scratch ----------------
#define F_Q    0LL
#define F_K    (F_Q + 2048LL*4096)
#define F_V    (F_K + 2048LL*1024)
#define F_G    (F_V + 2048LL*1024)
#define F_H1   (F_G + 2048LL*11008)
#define F_COS  (F_H1 + 2048LL*4096)
#define F_SIN  (F_COS + 2048LL*64)
#define F_MX   (F_SIN + 2048LL*64)
#define F_TOTAL (F_MX + 32LL*2048)

__device__ float g_f32[F_TOTAL];

// ---------------- bf16 scratch (hi, then lo at +half) ----------------
#define ZWQ   (4096LL*4096)
#define ZWKV  (4096LL*1024)
#define ZWO   (4096LL*4096)
#define ZWG   (4096LL*11008)
#define ZROT  (32LL*128*128)
#define ZX    (2048LL*4096)
#define ZKR   (2048LL*1024)
#define ZQH   (32LL*2048*128)
#define ZAO   (2048LL*4096)
#define ZMACT (2048LL*11008)

#define B_WQT   0LL
#define B_WKT   (B_WQT  + 2*ZWQ)
#define B_WVT   (B_WKT  + 2*ZWKV)
#define B_WOT   (B_WVT  + 2*ZWKV)
#define B_WGT   (B_WOT  + 2*ZWO)
#define B_WUT   (B_WGT  + 2*ZWG)
#define B_WDT   (B_WUT  + 2*ZWG)
#define B_ROT   (B_WDT  + 2*ZWG)
#define B_X     (B_ROT  + 2*ZROT)
#define B_QR    (B_X    + 2*ZX)
#define B_KR    (B_QR   + 2*ZX)
#define B_QH    (B_KR   + 2*ZKR)
#define B_KH    (B_QH   + 2*ZQH)
#define B_AO    (B_KH   + 2*ZQH)
#define B_Y     (B_AO   + 2*ZAO)
#define B_MACT  (B_Y    + 2*ZX)
#define B_TOTAL (B_MACT + 2*ZMACT)

__device__ __nv_bfloat16 g_bf[B_TOTAL];

// ---------------------------------------------------------------------------
// helpers
// ---------------------------------------------------------------------------
__device__ __forceinline__ unsigned f2tf(float x) {
    unsigned r;
    asm("cvt.rna.tf32.f32 %0, %1;" : "=r"(r) : "f"(x));
    return r;
}

__device__ __forceinline__ void split1(float v, __nv_bfloat16& h, __nv_bfloat16& l) {
    h = __float2bfloat16(v);
    l = __float2bfloat16(v - __bfloat162float(h));
}

__device__ __forceinline__ void store_split2(float v0, float v1,
                                             __nv_bfloat16* Chi, __nv_bfloat16* Clo,
                                             long long off) {
    unsigned h;
    asm("cvt.rn.bf16x2.f32 %0, %1, %2;" : "=r"(h) : "f"(v1), "f"(v0));
    float h0 = __uint_as_float(h << 16);
    float h1 = __uint_as_float(h & 0xffff0000u);
    unsigned l;
    asm("cvt.rn.bf16x2.f32 %0, %1, %2;" : "=r"(l) : "f"(v1 - h1), "f"(v0 - h0));
    *(unsigned*)(Chi + off) = h;
    *(unsigned*)(Clo + off) = l;
}

__device__ __forceinline__ void mma16bf(float* c, const unsigned* a, const unsigned* b) {
    asm volatile(
        "mma.sync.aligned.m16n8k16.row.col.f32.bf16.bf16.f32 "
        "{%0,%1,%2,%3},{%4,%5,%6,%7},{%8,%9},{%0,%1,%2,%3};"
        : "+f"(c[0]), "+f"(c[1]), "+f"(c[2]), "+f"(c[3])
        : "r"(a[0]), "r"(a[1]), "r"(a[2]), "r"(a[3]), "r"(b[0]), "r"(b[1]));
}

__device__ __forceinline__ void mma8tf(float* c, const unsigned* a,
                                       unsigned b0, unsigned b1) {
    asm volatile(
        "mma.sync.aligned.m16n8k8.row.col.f32.tf32.tf32.f32 "
        "{%0,%1,%2,%3},{%4,%5,%6,%7},{%8,%9},{%0,%1,%2,%3};"
        : "+f"(c[0]), "+f"(c[1]), "+f"(c[2]), "+f"(c[3])
        : "r"(a[0]), "r"(a[1]), "r"(a[2]), "r"(a[3]), "r"(b0), "r"(b1));
}

#define CP16(d, s) asm volatile("cp.async.cg.shared.global [%0], [%1], 16;" :: "r"(d), "l"(s))
#define CP_COMMIT() asm volatile("cp.async.commit_group;")
#define CP_WAIT0()  asm volatile("cp.async.wait_group 0;")

// ---------------------------------------------------------------------------
// RoPE tables (fp64)
// ---------------------------------------------------------------------------
__global__ void rope_table_kernel(float* cosT, float* sinT) {
    int s = blockIdx.x;
    int i = threadIdx.x;
    double inv = exp(-(double)i * (log(10000.0) / 64.0));
    double ang = (double)s * inv;
    double sv, cv;
    sincos(ang, &sv, &cv);
    cosT[s * 64 + i] = (float)cv;
    sinT[s * 64 + i] = (float)sv;
}

// ---------------------------------------------------------------------------
// transpose + split: dst[n][k] (bf16 hi/lo) = src[k][n] (f32)
// ---------------------------------------------------------------------------
__global__ void transpose_split_kernel(const float* __restrict__ src,
                                       __nv_bfloat16* __restrict__ dh,
                                       __nv_bfloat16* __restrict__ dl,
                                       int K, int N,
                                       long long sStride, long long dStride) {
    __shared__ float t[32][33];
    int z = blockIdx.z;
    src += z * sStride;
    dh += z * dStride;
    dl += z * dStride;
    int k0 = blockIdx.y * 32, n0 = blockIdx.x * 32;
    int tx = threadIdx.x;
#pragma unroll
    for (int i = threadIdx.y; i < 32; i += 8)
        t[i][tx] = src[(long long)(k0 + i) * N + n0 + tx];
    __syncthreads();
#pragma unroll
    for (int i = threadIdx.y; i < 32; i += 8) {
        float v = t[tx][i];
        __nv_bfloat16 h, l;
        split1(v, h, l);
        long long off = (long long)(n0 + i) * K + k0 + tx;
        dh[off] = h;
        dl[off] = l;
    }
}

// ---------------------------------------------------------------------------
// RMSNorm -> bf16 hi/lo
// ---------------------------------------------------------------------------
__global__ void rmsnorm_split_kernel(const float* __restrict__ x,
                                     const float* __restrict__ w,
                                     __nv_bfloat16* __restrict__ oh,
                                     __nv_bfloat16* __restrict__ ol) {
    int s = blockIdx.x;
    const float* row = x + (long long)s * D_DIM;
    int tid = threadIdx.x;
    float ss = 0.f;
    for (int i = tid; i < D_DIM; i += 256) {
        float v = row[i];
        ss += v * v;
    }
    __shared__ float red[256];
    red[tid] = ss;
    __syncthreads();
    for (int o = 128; o > 0; o >>= 1) {
        if (tid < o) red[tid] += red[tid + o];
        __syncthreads();
    }
    float inv = rsqrtf(red[0] / (float)D_DIM + EPS_C);
    long long base = (long long)s * D_DIM;
    for (int i = tid; i < D_DIM; i += 256) {
        float v = row[i] * inv * w[i];
        __nv_bfloat16 h, l;
        split1(v, h, l);
        oh[base + i] = h;
        ol[base + i] = l;
    }
}

// ---------------------------------------------------------------------------
// RoPE -> bf16 hi/lo
// ---------------------------------------------------------------------------
__global__ void rope_split_kernel(const float* __restrict__ in,
                                  __nv_bfloat16* __restrict__ oh,
                                  __nv_bfloat16* __restrict__ ol,
                                  const float* __restrict__ cosT,
                                  const float* __restrict__ sinT,
                                  int nHeads) {
    int s = blockIdx.x;
    int h = blockIdx.y;
    int d = threadIdx.x;
    int ld = nHeads * HD_DIM;
    long long base = (long long)s * ld + h * HD_DIM;
    float x = in[base + d];
    float other = (d < 64) ? -in[base + d + 64] : in[base + d - 64];
    float c = cosT[s * 64 + (d & 63)];
    float sn = sinT[s * 64 + (d & 63)];
    float v = x * c + other * sn;
    __nv_bfloat16 hh, ll;
    split1(v, hh, ll);
    oh[base + d] = hh;
    ol[base + d] = ll;
}

// ---------------------------------------------------------------------------
// row max over causal prefix
// ---------------------------------------------------------------------------
__global__ void rowmax_kernel(const float* __restrict__ t, float* __restrict__ mx) {
    int r = blockIdx.x * 8 + threadIdx.y;
    int s = r & (S_LEN - 1);
    const float* row = t + (long long)r * S_LEN;
    float m = -1e30f;
    for (int i = threadIdx.x; i <= s; i += 32) m = fmaxf(m, row[i]);
#pragma unroll
    for (int o = 16; o > 0; o >>= 1) m = fmaxf(m, __shfl_xor_sync(0xffffffffu, m, o));
    if (threadIdx.x == 0) mx[r] = m;
}

// ---------------------------------------------------------------------------
// bf16 TN GEMM: C[m,n] = sum_k A[m,k]*B[n,k], A/B pre-split hi/lo bf16.
// 128x128x32 tile, 8 warps (2x4), warp tile 64x32, 3 mma terms.
// ---------------------------------------------------------------------------
#define BSTR 40                      // bf16 row stride in smem
#define RSTR (BSTR / 2)              // u32 row stride (20)
#define ROW8 (8 * RSTR)              // +8 rows in u32 (fixed: was 8*RSTR*16)
#define TW   (128 * RSTR)            // u32 per matrix-stage
#define SMEM_BF_U32 (8 * TW)
#define SMEM_BF_BYTES (SMEM_BF_U32 * 4)

template <int EPI>
__global__ __launch_bounds__(256)
void gemm_bf(const __nv_bfloat16* __restrict__ Ah, const __nv_bfloat16* __restrict__ Al,
             const __nv_bfloat16* __restrict__ BhIn, const __nv_bfloat16* __restrict__ BlIn,
             float* __restrict__ CIn, __nv_bfloat16* __restrict__ Chi,
             __nv_bfloat16* __restrict__ Clo, const float* __restrict__ R,
             int M, int N, int K, int lda, int ldb, int ldcIn,
             long long strideA, int aRep,
             long long strideB, int bRep,
             long long strideC, float alpha,
             const __nv_bfloat16* __restrict__ B2h, const __nv_bfloat16* __restrict__ B2l,
             const __nv_bfloat16* __restrict__ B3h, const __nv_bfloat16* __restrict__ B3l,
             float* __restrict__ C2, float* __restrict__ C3) {
    extern __shared__ unsigned smem_u[];

    int z = blockIdx.z;
    Ah += (long long)(z / aRep) * strideA;
    Al += (long long)(z / aRep) * strideA;
    const __nv_bfloat16* Bh = BhIn + (long long)(z / bRep) * strideB;
    const __nv_bfloat16* Bl = BlIn + (long long)(z / bRep) * strideB;
    float* C = CIn + (long long)z * strideC;
    if (EPI == 2 || EPI == 5) {
        Chi += (long long)z * strideC;
        Clo += (long long)z * strideC;
    }
    int ldc = ldcIn;
    int col0 = blockIdx.x * 128;

    if (B2h != nullptr) {
        if (col0 >= 5120)      { Bh = B3h; Bl = B3l; C = C3; ldc = 1024; col0 -= 5120; }
        else if (col0 >= 4096) { Bh = B2h; Bl = B2l; C = C2; ldc = 1024; col0 -= 4096; }
    }

    const int tid = threadIdx.x;
    const int row0 = blockIdx.y * 128;
    const int warp = tid >> 5;
    const int lane = tid & 31;
    const int gid = lane >> 2;
    const int t4 = lane & 3;
    const int wm = (warp & 1) * 64;
    const int wn = (warp >> 1) * 32;

    float acc[4][4][4];
#pragma unroll
    for (int i = 0; i < 4; i++)
#pragma unroll
        for (int j = 0; j < 4; j++)
#pragma unroll
            for (int q = 0; q < 4; q++) acc[i][j][q] = 0.f;

    const int r = tid >> 1;
    const int cb = (tid & 1) * 16;
    const int nIter = K / 32;

#define LOAD_STAGE(k0, s)                                                              \
    {                                                                                  \
        const __nv_bfloat16* sa = Ah + (long long)(row0 + r) * lda + (k0) + cb;        \
        const __nv_bfloat16* sal = Al + (long long)(row0 + r) * lda + (k0) + cb;       \
        const __nv_bfloat16* sb = Bh + (long long)(col0 + r) * ldb + (k0) + cb;        \
        const __nv_bfloat16* sbl = Bl + (long long)(col0 + r) * ldb + (k0) + cb;       \
        unsigned wbase = r * RSTR + cb / 2;                                            \
        unsigned dA = (unsigned)__cvta_generic_to_shared(smem_u + (s)*TW + wbase);     \
        unsigned dAl = (unsigned)__cvta_generic_to_shared(smem_u + 2*TW + (s)*TW + wbase); \
        unsigned dB = (unsigned)__cvta_generic_to_shared(smem_u + 4*TW + (s)*TW + wbase);  \
        unsigned dBl = (unsigned)__cvta_generic_to_shared(smem_u + 6*TW + (s)*TW + wbase); \
        CP16(dA, sa); CP16(dA + 16, sa + 8);                                           \
        CP16(dAl, sal); CP16(dAl + 16, sal + 8);                                       \
        CP16(dB, sb); CP16(dB + 16, sb + 8);                                           \
        CP16(dBl, sbl); CP16(dBl + 16, sbl + 8);                                       \
        CP_COMMIT();                                                                   \
    }

    LOAD_STAGE(0, 0)

    for (int it = 0; it < nIter; it++) {
        int buf = it & 1;
        CP_WAIT0();
        __syncthreads();

        if (it + 1 < nIter) {
            LOAD_STAGE((it + 1) * 32, buf ^ 1)
        }

        const unsigned* AhS = smem_u + buf * TW;
        const unsigned* AlS = smem_u + 2 * TW + buf * TW;
        const unsigned* BhS = smem_u + 4 * TW + buf * TW;
        const unsigned* BlS = smem_u + 6 * TW + buf * TW;

#pragma unroll
        for (int ks = 0; ks < 2; ks++) {
            int kw = ks * 8 + t4;
            unsigned bh[4][2], bl[4][2];
#pragma unroll
            for (int j = 0; j < 4; j++) {
                int nb = (wn + j * 8 + gid) * RSTR + kw;
                bh[j][0] = BhS[nb];
                bh[j][1] = BhS[nb + 4];
                bl[j][0] = BlS[nb];
                bl[j][1] = BlS[nb + 4];
            }
#pragma unroll
            for (int i = 0; i < 4; i++) {
                int ab = (wm + i * 16 + gid) * RSTR + kw;
                unsigned ah[4] = {AhS[ab], AhS[ab + ROW8], AhS[ab + 4], AhS[ab + ROW8 + 4]};
                unsigned al[4] = {AlS[ab], AlS[ab + ROW8], AlS[ab + 4], AlS[ab + ROW8 + 4]};
#pragma unroll
                for (int j = 0; j < 4; j++) {
                    mma16bf(acc[i][j], ah, bh[j]);
                    mma16bf(acc[i][j], al, bh[j]);
                    mma16bf(acc[i][j], ah, bl[j]);
                }
            }
        }
        __syncthreads();
    }
#undef LOAD_STAGE

    // epilogue
#pragma unroll
    for (int i = 0; i < 4; i++)
#pragma unroll
        for (int j = 0; j < 4; j++)
#pragma unroll
            for (int h = 0; h < 2; h++) {
                int rr_ = row0 + wm + i * 16 + gid + h * 8;
                int c = col0 + wn + j * 8 + t4 * 2;
                float v0 = acc[i][j][h * 2 + 0];
                float v1 = acc[i][j][h * 2 + 1];
                long long off = (long long)rr_ * ldc + c;
                if (EPI == 0) {
                    float2 o2; o2.x = v0; o2.y = v1;
                    *(float2*)(C + off) = o2;
                } else if (EPI == 1) {
                    float2 o2; o2.x = v0 * alpha; o2.y = v1 * alpha;
                    *(float2*)(C + off) = o2;
                } else if (EPI == 2) {
                    v0 *= alpha; v1 *= alpha;
                    v0 = v0 / (1.f + fabsf(v0));
                    v1 = v1 / (1.f + fabsf(v1));
                    store_split2(v0, v1, Chi, Clo, off);
                } else if (EPI == 3) {
                    float2 rv = *(const float2*)(R + off);
                    float2 o2; o2.x = v0 + rv.x; o2.y = v1 + rv.y;
                    *(float2*)(C + off) = o2;
                } else if (EPI == 5) {
                    float2 rv = *(const float2*)(R + off);
                    float s0 = rv.x / (1.f + __expf(-rv.x));
                    float s1 = rv.y / (1.f + __expf(-rv.y));
                    store_split2(v0 * s0, v1 * s1, Chi, Clo, off);
                }
            }
}

// ---------------------------------------------------------------------------
// PV kernel: tf32, A = true_attn f32 (softmax in smem), B = V f32 NN.
// Writes attn_out bf16 hi/lo. Per-head: M=2048, N=128, K=row0+128 (causal).
// ---------------------------------------------------------------------------
#define ASTR 36
#define BSTR_NN 136
#define ABUF (128 * ASTR)
#define PV_SMEM_FLOATS (2 * ABUF + 2 * ABUF + 128 + 128 + 256)
#define PV_SMEM_BYTES (PV_SMEM_FLOATS * 4)

__global__ __launch_bounds__(256)
void gemm_pv(const float* __restrict__ Ain, const float* __restrict__ Bin,
             __nv_bfloat16* __restrict__ ChiIn, __nv_bfloat16* __restrict__ CloIn,
             const float* __restrict__ stats) {
    extern __shared__ float smem[];
    float* As = smem;
    float* Bs = smem + 2 * ABUF;
    float* sMax = smem + 4 * ABUF;
    float* sSum = sMax + 128;
    float* sPart = sSum + 128;

    const int M = S_LEN, K = S_LEN;
    const int lda = S_LEN, ldb = 1024, ldc = D_DIM;

    int z = blockIdx.z;
    const float* A = Ain + (long long)z * S_LEN * S_LEN;
    const float* B = Bin + (long long)(z / 4) * 128;
    __nv_bfloat16* Chi = ChiIn + (long long)z * 128;
    __nv_bfloat16* Clo = CloIn + (long long)z * 128;

    const int tid = threadIdx.x;
    const int row0 = blockIdx.y * 128;
    const int warp = tid >> 5;
    const int lane = tid & 31;
    const int gid = lane >> 2;
    const int t4 = lane & 3;
    const int wm = (warp & 1) * 64;
    const int wn = (warp >> 1) * 32;

    if (tid < 128) {
        sMax[tid] = stats[(long long)z * M + row0 + tid];
        sSum[tid] = 0.f;
    }
    __syncthreads();

    float acc[4][4][4];
#pragma unroll
    for (int i = 0; i < 4; i++)
#pragma unroll
        for (int j = 0; j < 4; j++)
#pragma unroll
            for (int q = 0; q < 4; q++) acc[i][j][q] = 0.f;

    int Kend = (row0 + 128 < K) ? row0 + 128 : K;
    int nIter = Kend / 32;

    const int arow = tid >> 1, acol = (tid & 1) * 16;
    const int brow = tid >> 3, bcol = (tid & 7) * 16;

    {
        const float* src = A + (long long)(row0 + arow) * lda + acol;
        unsigned dst = (unsigned)__cvta_generic_to_shared(As + arow * ASTR + acol);
#pragma unroll
        for (int i = 0; i < 4; i++) CP16(dst + i * 16, src + i * 4);
        const float* bs = B + (long long)brow * ldb + bcol;
        unsigned bd = (unsigned)__cvta_generic_to_shared(Bs + brow * BSTR_NN + bcol);
#pragma unroll
        for (int i = 0; i < 4; i++) CP16(bd + i * 16, bs + i * 4);
        CP_COMMIT();
    }

    for (int it = 0; it < nIter; it++) {
        int buf = it & 1;
        CP_WAIT0();
        __syncthreads();

        {
            int rr_ = tid >> 1, c0 = (tid & 1) * 16;
            float* p = As + buf * ABUF + rr_ * ASTR + c0;
            int gm = row0 + rr_;
            float mxv = sMax[rr_];
            int k0 = it * 32;
            float part = 0.f;
#pragma unroll
            for (int i = 0; i < 16; i++) {
                int gk = k0 + c0 + i;
                float val = 0.f;
                if (gk <= gm) val = __expf(p[i] - mxv);
                val = __uint_as_float(f2tf(val));
                p[i] = val;
                part += val;
            }
            sPart[tid] = part;
            __syncthreads();
            if (tid < 128) sSum[tid] += sPart[2 * tid] + sPart[2 * tid + 1];
            __syncthreads();
        }

        if (it + 1 < nIter) {
            int k0n = (it + 1) * 32;
            int nb = buf ^ 1;
            const float* src = A + (long long)(row0 + arow) * lda + k0n + acol;
            unsigned dst = (unsigned)__cvta_generic_to_shared(As + nb * ABUF + arow * ASTR + acol);
#pragma unroll
            for (int i = 0; i < 4; i++) CP16(dst + i * 16, src + i * 4);
            const float* bs = B + (long long)(k0n + brow) * ldb + bcol;
            unsigned bd = (unsigned)__cvta_generic_to_shared(Bs + nb * ABUF + brow * BSTR_NN + bcol);
#pragma unroll
            for (int i = 0; i < 4; i++) CP16(bd + i * 16, bs + i * 4);
            CP_COMMIT();
        }

        const float* Ab = As + buf * ABUF;
        const float* Bb = Bs + buf * ABUF;
#pragma unroll
        for (int ks = 0; ks < 4; ks++) {
            int k = ks * 8;
            unsigned af[4][4];
#pragma unroll
            for (int i = 0; i < 4; i++) {
                const float* ap = Ab + (wm + i * 16 + gid) * ASTR + k + t4;
                af[i][0] = f2tf(ap[0]);
                af[i][1] = f2tf(ap[8 * ASTR]);
                af[i][2] = f2tf(ap[4]);
                af[i][3] = f2tf(ap[8 * ASTR + 4]);
            }
            unsigned bf2[4][2];
#pragma unroll
            for (int j = 0; j < 4; j++) {
                const float* bp = Bb + (k + t4) * BSTR_NN + wn + j * 8 + gid;
                bf2[j][0] = f2tf(bp[0]);
                bf2[j][1] = f2tf(bp[4 * BSTR_NN]);
            }
#pragma unroll
            for (int i = 0; i < 4; i++)
#pragma unroll
                for (int j = 0; j < 4; j++)
                    mma8tf(acc[i][j], af[i], bf2[j][0], bf2[j][1]);
        }
    }

#pragma unroll
    for (int i = 0; i < 4; i++)
#pragma unroll
        for (int j = 0; j < 4; j++)
#pragma unroll
            for (int h = 0; h < 2; h++) {
                int lr = wm + i * 16 + gid + h * 8;
                int rr_ = row0 + lr;
                int c = wn + j * 8 + t4 * 2;
                float sdiv = sSum[lr];
                float v0 = acc[i][j][h * 2 + 0] / sdiv;
                float v1 = acc[i][j][h * 2 + 1] / sdiv;
                long long off = (long long)rr_ * ldc + c;
                store_split2(v0, v1, Chi, Clo, off);
            }
}

// ---------------------------------------------------------------------------
// launch
// ---------------------------------------------------------------------------
extern "C" void kernel_launch(void* const* d_in, const int* in_sizes, int n_in,
                              void* d_out, int out_size) {
    const float* hidden_states = (const float*)d_in[0];
    const float* ln1_w = (const float*)d_in[1];
    const float* ln2_w = (const float*)d_in[2];
    const float* Wq = (const float*)d_in[3];
    const float* Wk = (const float*)d_in[4];
    const float* Wv = (const float*)d_in[5];
    const float* Wo = (const float*)d_in[6];
    const float* rot_mat = (const float*)d_in[7];
    const float* Wg = (const float*)d_in[8];
    const float* Wu = (const float*)d_in[9];
    const float* Wd = (const float*)d_in[10];

    float* out = (float*)d_out;
    float* out_hidden = out;
    float* out_draft = out + 2048LL * 4096;
    float* out_true = out_draft + (long long)H_HEADS * S_LEN * S_LEN;

    float* f = nullptr;
    cudaGetSymbolAddress((void**)&f, g_f32);
    __nv_bfloat16* b = nullptr;
    cudaGetSymbolAddress((void**)&b, g_bf);

    float* g_q = f + F_Q;
    float* g_k = f + F_K;
    float* g_v = f + F_V;
    float* g_g = f + F_G;
    float* g_h1 = f + F_H1;
    float* g_cos = f + F_COS;
    float* g_sin = f + F_SIN;
    float* g_mx = f + F_MX;

#define HB(name) (b + name)
#define LB(name, sz) (b + name + sz)
    __nv_bfloat16 *wqtH = HB(B_WQT), *wqtL = LB(B_WQT, ZWQ);
    __nv_bfloat16 *wktH = HB(B_WKT), *wktL = LB(B_WKT, ZWKV);
    __nv_bfloat16 *wvtH = HB(B_WVT), *wvtL = LB(B_WVT, ZWKV);
    __nv_bfloat16 *wotH = HB(B_WOT), *wotL = LB(B_WOT, ZWO);
    __nv_bfloat16 *wgtH = HB(B_WGT), *wgtL = LB(B_WGT, ZWG);
    __nv_bfloat16 *wutH = HB(B_WUT), *wutL = LB(B_WUT, ZWG);
    __nv_bfloat16 *wdtH = HB(B_WDT), *wdtL = LB(B_WDT, ZWG);
    __nv_bfloat16 *rotH = HB(B_ROT), *rotL = LB(B_ROT, ZROT);
    __nv_bfloat16 *xH = HB(B_X), *xL = LB(B_X, ZX);
    __nv_bfloat16 *qrH = HB(B_QR), *qrL = LB(B_QR, ZX);
    __nv_bfloat16 *krH = HB(B_KR), *krL = LB(B_KR, ZKR);
    __nv_bfloat16 *qhH = HB(B_QH), *qhL = LB(B_QH, ZQH);
    __nv_bfloat16 *khH = HB(B_KH), *khL = LB(B_KH, ZQH);
    __nv_bfloat16 *aoH = HB(B_AO), *aoL = LB(B_AO, ZAO);
    __nv_bfloat16 *yH = HB(B_Y), *yL = LB(B_Y, ZX);
    __nv_bfloat16 *mH = HB(B_MACT), *mL = LB(B_MACT, ZMACT);

    const float scale = 0.08838834764831843f;

    cudaFuncSetAttribute(gemm_bf<0>, cudaFuncAttributeMaxDynamicSharedMemorySize, SMEM_BF_BYTES);
    cudaFuncSetAttribute(gemm_bf<1>, cudaFuncAttributeMaxDynamicSharedMemorySize, SMEM_BF_BYTES);
    cudaFuncSetAttribute(gemm_bf<2>, cudaFuncAttributeMaxDynamicSharedMemorySize, SMEM_BF_BYTES);
    cudaFuncSetAttribute(gemm_bf<3>, cudaFuncAttributeMaxDynamicSharedMemorySize, SMEM_BF_BYTES);
    cudaFuncSetAttribute(gemm_bf<5>, cudaFuncAttributeMaxDynamicSharedMemorySize, SMEM_BF_BYTES);
    cudaFuncSetAttribute(gemm_pv, cudaFuncAttributeMaxDynamicSharedMemorySize, PV_SMEM_BYTES);

    // ---- weight transposes + splits ----
    transpose_split_kernel<<<dim3(128, 128), dim3(32, 8)>>>(Wq, wqtH, wqtL, 4096, 4096, 0, 0);
    transpose_split_kernel<<<dim3(32, 128), dim3(32, 8)>>>(Wk, wktH, wktL, 4096, 1024, 0, 0);
    transpose_split_kernel<<<dim3(32, 128), dim3(32, 8)>>>(Wv, wvtH, wvtL, 4096, 1024, 0, 0);
    transpose_split_kernel<<<dim3(128, 128), dim3(32, 8)>>>(Wo, wotH, wotL, 4096, 4096, 0, 0);
    transpose_split_kernel<<<dim3(344, 128), dim3(32, 8)>>>(Wg, wgtH, wgtL, 4096, FF_DIM, 0, 0);
    transpose_split_kernel<<<dim3(344, 128), dim3(32, 8)>>>(Wu, wutH, wutL, 4096, FF_DIM, 0, 0);
    transpose_split_kernel<<<dim3(128, 344), dim3(32, 8)>>>(Wd, wdtH, wdtL, FF_DIM, 4096, 0, 0);
    transpose_split_kernel<<<dim3(4, 4, 32), dim3(32, 8)>>>(rot_mat, rotH, rotL, 128, 128,
                                                           128LL * 128, 128LL * 128);

    rope_table_kernel<<<S_LEN, 64>>>(g_cos, g_sin);
    rmsnorm_split_kernel<<<S_LEN, 256>>>(hidden_states, ln1_w, xH, xL);

    // fused QKV (f32 out): N = 4096|1024|1024
    gemm_bf<0><<<dim3(48, 16, 1), 256, SMEM_BF_BYTES>>>(
        xH, xL, wqtH, wqtL, g_q, nullptr, nullptr, nullptr,
        S_LEN, 6144, 4096, 4096, 4096, 4096, 0, 1, 0, 1, 0, 0.f,
        wktH, wktL, wvtH, wvtL, g_k, g_v);

    // RoPE -> bf16 splits
    rope_split_kernel<<<dim3(S_LEN, H_HEADS), 128>>>(g_q, qrH, qrL, g_cos, g_sin, H_HEADS);
    rope_split_kernel<<<dim3(S_LEN, HKV_HEADS), 128>>>(g_k, krH, krL, g_cos, g_sin, HKV_HEADS);

    // hash GEMMs -> qh/kh bf16 splits
    gemm_bf<2><<<dim3(1, 16, 32), 256, SMEM_BF_BYTES>>>(
        qrH, qrL, rotH, rotL, nullptr, qhH, qhL, nullptr,
        S_LEN, 128, 128, 4096, 128, 128, 128, 1, 128LL * 128, 1,
        2048LL * 128, GAMMA_C, nullptr, nullptr, nullptr, nullptr, nullptr, nullptr);
    gemm_bf<2><<<dim3(1, 16, 32), 256, SMEM_BF_BYTES>>>(
        krH, krL, rotH, rotL, nullptr, khH, khL, nullptr,
        S_LEN, 128, 128, 1024, 128, 128, 128, 4, 128LL * 128, 1,
        2048LL * 128, GAMMA_C, nullptr, nullptr, nullptr, nullptr, nullptr, nullptr);

    // draft_attn = q_hash @ k_hash^T
    gemm_bf<0><<<dim3(16, 16, 32), 256, SMEM_BF_BYTES>>>(
        qhH, qhL, khH, khL, out_draft, nullptr, nullptr, nullptr,
        S_LEN, S_LEN, 128, 128, 128, S_LEN, 2048LL * 128, 1, 2048LL * 128, 1,
        (long long)S_LEN * S_LEN, 0.f, nullptr, nullptr, nullptr, nullptr, nullptr, nullptr);

    // true_attn = scale * q_r @ k_r^T
    gemm_bf<1><<<dim3(16, 16, 32), 256, SMEM_BF_BYTES>>>(
        qrH, qrL, krH, krL, out_true, nullptr, nullptr, nullptr,
        S_LEN, S_LEN, 128, 4096, 1024, S_LEN, 128, 1, 128, 4,
        (long long)S_LEN * S_LEN, scale, nullptr, nullptr, nullptr, nullptr, nullptr, nullptr);

    // causal row max + PV (writes ao bf16 splits)
    rowmax_kernel<<<H_HEADS * S_LEN / 8, dim3(32, 8)>>>(out_true, g_mx);
    gemm_pv<<<dim3(1, 16, 32), 256, PV_SMEM_BYTES>>>(out_true, g_v, aoH, aoL, g_mx);

    // o_proj + residual
    gemm_bf<3><<<dim3(32, 16, 1), 256, SMEM_BF_BYTES>>>(
        aoH, aoL, wotH, wotL, g_h1, nullptr, nullptr, hidden_states,
        S_LEN, 4096, 4096, 4096, 4096, 4096, 0, 1, 0, 1, 0, 0.f,
        nullptr, nullptr, nullptr, nullptr, nullptr, nullptr);

    rmsnorm_split_kernel<<<S_LEN, 256>>>(g_h1, ln2_w, yH, yL);

    // MLP
    gemm_bf<0><<<dim3(86, 16, 1), 256, SMEM_BF_BYTES>>>(
        yH, yL, wgtH, wgtL, g_g, nullptr, nullptr, nullptr,
        S_LEN, FF_DIM, 4096, 4096, 4096, FF_DIM, 0, 1, 0, 1, 0, 0.f,
        nullptr, nullptr, nullptr, nullptr, nullptr, nullptr);
    gemm_bf<5><<<dim3(86, 16, 1), 256, SMEM_BF_BYTES>>>(
        yH, yL, wutH, wutL, nullptr, mH, mL, g_g,
        S_LEN, FF_DIM, 4096, 4096, 4096, FF_DIM, 0, 1, 0, 1, 0, 0.f,
        nullptr, nullptr, nullptr, nullptr, nullptr, nullptr);
    gemm_bf<3><<<dim3(32, 16, 1), 256, SMEM_BF_BYTES>>>(
        mH, mL, wdtH, wdtL, out_hidden, nullptr, nullptr, g_h1,
        S_LEN, 4096, FF_DIM, FF_DIM, FF_DIM, 4096, 0, 1, 0, 1, 0, 0.f,
        nullptr, nullptr, nullptr, nullptr, nullptr, nullptr);

    (void)in_sizes; (void)n_in; (void)out_size;
}